// round 17
// baseline (speedup 1.0000x reference)
#include <cuda_runtime.h>
#include <cuda_fp16.h>
#include <cstdint>
#include <cstddef>

#define NE 8192
#define NF 64
#define NH 256
#define NN (128*8192)
#define R48 48
#define NGT48 21846          // ceil(2^20 / 48); last tile has 16 valid rows
#define NTHREADS 384

// smem byte offsets
#define OFF_BUF  0u          // 3 x 24KB shared sA(12KB)/sH(24KB) buffer per group
#define BUF_STRIDE 24576u
#define OFF_SW1  73728u      // W1^T [256n][128k] f16 (64KB)
#define OFF_SW2  139264u     // W2^T [128n][256k] f16 (64KB)
#define OFF_SB2  204800u
#define OFF_FLG  205312u     // 3 x u32 mismatch flags
#define SMEM_REQ 205440

__device__ __forceinline__ uint32_t smem_u32(const void* p){
    uint32_t a;
    asm("{ .reg .u64 t; cvta.to.shared.u64 t, %1; cvt.u32.u64 %0, t; }" : "=r"(a) : "l"(p));
    return a;
}
__device__ __forceinline__ uint32_t pack_h2(float a, float b){
    __half2 h = __floats2half2_rn(a, b);
    return *reinterpret_cast<uint32_t*>(&h);
}
__device__ __forceinline__ void ldmx4(uint32_t& a0, uint32_t& a1, uint32_t& a2, uint32_t& a3, uint32_t addr){
    asm volatile("ldmatrix.sync.aligned.m8n8.x4.shared.b16 {%0,%1,%2,%3}, [%4];"
                 : "=r"(a0), "=r"(a1), "=r"(a2), "=r"(a3) : "r"(addr));
}
__device__ __forceinline__ uint32_t lds32(uint32_t addr){
    uint32_t v; asm volatile("ld.shared.b32 %0, [%1];" : "=r"(v) : "r"(addr)); return v;
}
__device__ __forceinline__ void sts32(uint32_t addr, uint32_t v){
    asm volatile("st.shared.b32 [%0], %1;" :: "r"(addr), "r"(v) : "memory");
}
__device__ __forceinline__ void sts64(uint32_t addr, uint32_t v0, uint32_t v1){
    asm volatile("st.shared.v2.b32 [%0], {%1,%2};" :: "r"(addr), "r"(v0), "r"(v1) : "memory");
}
__device__ __forceinline__ void sts128(uint32_t addr, uint32_t p0, uint32_t p1, uint32_t p2, uint32_t p3){
    asm volatile("st.shared.v4.b32 [%0], {%1,%2,%3,%4};" :: "r"(addr), "r"(p0), "r"(p1), "r"(p2), "r"(p3) : "memory");
}
__device__ __forceinline__ void mma16(float c[4], uint32_t a0, uint32_t a1, uint32_t a2, uint32_t a3,
                                      uint32_t b0, uint32_t b1){
    asm volatile(
        "mma.sync.aligned.m16n8k16.row.col.f32.f16.f16.f32 "
        "{%0,%1,%2,%3},{%4,%5,%6,%7},{%8,%9},{%0,%1,%2,%3};\n"
        : "+f"(c[0]), "+f"(c[1]), "+f"(c[2]), "+f"(c[3])
        : "r"(a0), "r"(a1), "r"(a2), "r"(a3), "r"(b0), "r"(b1));
}
__device__ __forceinline__ uint32_t relu_bias_h2(float a, float b, uint32_t bias){
    __half2 v = __floats2half2_rn(a, b);
    __half2 bb = *reinterpret_cast<__half2*>(&bias);
    v = __hmax2(__hadd2(v, bb), __float2half2_rn(0.f));
    return *reinterpret_cast<uint32_t*>(&v);
}

__global__ void __launch_bounds__(NTHREADS, 1)
fused_h16p(const float* __restrict__ x,  const float* __restrict__ gf,
           const float* __restrict__ W1, const float* __restrict__ b1g,
           const float* __restrict__ W2, const float* __restrict__ b2g,
           const int*   __restrict__ pidx, float* __restrict__ out, int write_event)
{
    extern __shared__ char sm[];
    const int tid  = threadIdx.x;
    const int warp = tid >> 5, lane = tid & 31;
    const int grp = lane >> 2, tig = lane & 3;
    const int wg = warp >> 2, wn = warp & 3;   // 3 groups x 4 n-warps
    const int tid_g = tid & 127;

    const uint32_t smu  = smem_u32(sm);
    const uint32_t buf_g = smu + OFF_BUF + (uint32_t)wg * BUF_STRIDE;
    const uint32_t flagA = smu + OFF_FLG + (uint32_t)wg * 4u;
    float* sb2 = (float*)(sm + OFF_SB2);

    // ---- one-time weight preload (swizzled f16) ----
    for (int i = tid; i < 128 * NH; i += NTHREADS) {
        int k = i >> 8, n = i & 255;
        uint32_t cb = (uint32_t)(2 * k);
        uint32_t off = (uint32_t)n * 256u + ((cb & ~15u) ^ (((uint32_t)n & 7u) << 4)) + (cb & 15u);
        *(half*)(sm + OFF_SW1 + off) = __float2half_rn(W1[i]);
    }
    for (int i = tid; i < NH * 128; i += NTHREADS) {
        int k = i >> 7, n = i & 127;
        uint32_t cb = (uint32_t)(2 * k);
        uint32_t off = (uint32_t)n * 512u + ((cb & ~15u) ^ (((uint32_t)n & 7u) << 4)) + (cb & 15u);
        *(half*)(sm + OFF_SW2 + off) = __float2half_rn(W2[i]);
    }
    if (tid < 128) sb2[tid] = b2g[tid];
    if (tid_g == 0) sts32(flagA, 0u);
    __syncthreads();   // last CTA-wide sync

    // per-thread constants
    const uint32_t amask = ((uint32_t)(lane & 7)) << 4;
    const uint32_t ahi   = ((uint32_t)(lane >> 4)) << 4;
    const int lr = lane & 15;

    const uint32_t browSel = (uint32_t)(((lane & 16) >> 1) + (lane & 7));
    const uint32_t bq      = (uint32_t)((lane & 8) << 1);
    const uint32_t bmsk    = ((uint32_t)(lane & 7)) << 4;

    const int nb1 = wn * 64;
    const int nb2 = wn * 32;
    const uint32_t b1Ldsm = smu + OFF_SW1 + ((uint32_t)nb1 + browSel) * 256u;
    const uint32_t b2Ldsm = smu + OFF_SW2 + ((uint32_t)nb2 + browSel) * 512u;

    uint32_t a1Base[3], a2Base[3];
    #pragma unroll
    for (int mf = 0; mf < 3; mf++) {
        a1Base[mf] = buf_g + (uint32_t)(16*mf + lr) * 256u;
        a2Base[mf] = buf_g + (uint32_t)(16*mf + lr) * 512u;
    }

    // cached packed b1 bias (tile-invariant per thread)
    uint32_t bh2[8];
    #pragma unroll
    for (int nt = 0; nt < 8; nt++) {
        const int c0 = nb1 + nt*8 + 2*tig;
        bh2[nt] = pack_h2(b1g[c0], b1g[c0+1]);
    }

    // phase-A assignments: gf gather 2 threads/row (96 threads), copy 128 threads x 6 uint4
    const int gr2 = tid_g >> 1, gq2 = tid_g & 1;   // gf row 0..47, half 0/1 (valid tid_g<96)
    const bool gact = (tid_g < 96);

    const int G0    = blockIdx.x * 3 + wg;
    const int gstep = gridDim.x * 3;
    int pi_cur = 0;
    if (gact && G0 < NGT48) {
        int rr = G0 * R48 + gr2;
        if (rr < NN) pi_cur = pidx[rr];
    }

    #define BARG() asm volatile("bar.sync %0, 128;" :: "r"(wg + 4) : "memory")

    // ================= persistent group-tile loop =================
    for (int mb = G0; mb < NGT48; mb += gstep) {
        const int rowbase_t = mb * R48;

        // ---- Phase A: merged gather + identity copy + event ----
        {
            // identity copy: 48 rows = 768 uint4, guarded for tail
            const size_t g4 = (size_t)mb * 768;
            uint4 cc[6];
            #pragma unroll
            for (int j = 0; j < 6; j++) {
                size_t gi = g4 + (size_t)(tid_g + 128*j);
                cc[j] = make_uint4(0u,0u,0u,0u);
                if (gi < (size_t)NN * 16) cc[j] = ((const uint4*)x)[gi];
            }
            #pragma unroll
            for (int j = 0; j < 6; j++) {
                size_t gi = g4 + (size_t)(tid_g + 128*j);
                if (gi < (size_t)NN * 16) ((uint4*)out)[gi] = cc[j];
            }

            // gf gather (rows 0..47, 2 threads/row, 32 floats each)
            if (gact) {
                const int rr = rowbase_t + gr2;
                if (rr < NN && pi_cur != rr) sts32(flagA, 1u);
                const float4* gs = (const float4*)(gf + (size_t)(((unsigned)pi_cur) & (NE-1)) * NF) + gq2 * 8;
                float4 g[8];
                #pragma unroll
                for (int c = 0; c < 8; c++) g[c] = gs[c];
                const uint32_t rb  = buf_g + (uint32_t)gr2 * 256u;
                const uint32_t msk = ((uint32_t)(gr2 & 7)) << 4;
                #pragma unroll
                for (int c = 0; c < 4; c++) {
                    sts128(rb + ((128u + (uint32_t)gq2 * 64u + (uint32_t)(c*16)) ^ msk),
                           pack_h2(g[2*c].x, g[2*c].y),   pack_h2(g[2*c].z, g[2*c].w),
                           pack_h2(g[2*c+1].x, g[2*c+1].y), pack_h2(g[2*c+1].z, g[2*c+1].w));
                }
            }

            // x part STS from copy regs (fast path: x[row] == x[pidx[row]])
            {
                const uint32_t colu = (uint32_t)((tid_g & 15) >> 1) * 16u;
                const uint32_t sub  = (uint32_t)(tid_g & 1) * 8u;
                const int rbase = tid_g >> 4;
                #pragma unroll
                for (int j = 0; j < 6; j++) {
                    const int rj = rbase + 8 * j;   // 0..47
                    const float4 f = *(float4*)&cc[j];
                    const uint32_t addr = buf_g + (uint32_t)rj * 256u
                                        + (colu ^ (((uint32_t)(rj & 7)) << 4)) + sub;
                    sts64(addr, pack_h2(f.x, f.y), pack_h2(f.z, f.w));
                }
            }
            // event fill: 144 per tile
            if (write_event) {
                int ei = mb * 144 + tid_g;
                if (ei < 3 * NN) out[(size_t)3 * NN * NF + ei] = (float)(ei & (NE - 1));
                if (tid_g < 16) {
                    int e2 = mb * 144 + 128 + tid_g;
                    if (e2 < 3 * NN) out[(size_t)3 * NN * NF + e2] = (float)(e2 & (NE - 1));
                }
            }
        }
        BARG();   // B1: sA ready

        // ---- repair path (group-uniform; never taken for arange pidx) ----
        if (lds32(flagA) != 0u) {
            if (gact) {
                const float4* xsrc = (const float4*)(x + (size_t)pi_cur * NF) + gq2 * 8;
                float4 h[8];
                #pragma unroll
                for (int c = 0; c < 8; c++) h[c] = xsrc[c];
                const uint32_t rb  = buf_g + (uint32_t)gr2 * 256u;
                const uint32_t msk = ((uint32_t)(gr2 & 7)) << 4;
                #pragma unroll
                for (int c = 0; c < 4; c++) {
                    sts128(rb + (((uint32_t)gq2 * 64u + (uint32_t)(c*16)) ^ msk),
                           pack_h2(h[2*c].x, h[2*c].y),   pack_h2(h[2*c].z, h[2*c].w),
                           pack_h2(h[2*c+1].x, h[2*c+1].y), pack_h2(h[2*c+1].z, h[2*c+1].w));
                }
            }
            if (tid_g == 0) sts32(flagA, 0u);
            BARG();
        }

        // prefetch next tile's pidx
        {
            int mn = mb + gstep;
            if (gact && mn < NGT48) {
                int rr = mn * R48 + gr2;
                if (rr < NN) pi_cur = pidx[rr];
            }
        }

        // ---- GEMM1: C1(48x256) = A(48x128) @ W1 ----
        float acc1[3][8][4];
        #pragma unroll
        for (int mf=0; mf<3; mf++)
            #pragma unroll
            for (int nt=0; nt<8; nt++)
                #pragma unroll
                for (int i=0;i<4;i++) acc1[mf][nt][i]=0.f;

        #pragma unroll
        for (int kk = 0; kk < 8; kk++) {
            const uint32_t ksw  = (((uint32_t)(kk*32)) + ahi) ^ amask;
            const uint32_t koff = (((uint32_t)(kk*32)) + bq)  ^ bmsk;
            uint32_t A[3][4];
            #pragma unroll
            for (int mf = 0; mf < 3; mf++)
                ldmx4(A[mf][0],A[mf][1],A[mf][2],A[mf][3], a1Base[mf] + ksw);
            #pragma unroll
            for (int j = 0; j < 4; j++) {
                uint32_t b0,b1,b2,b3;
                ldmx4(b0,b1,b2,b3, b1Ldsm + (uint32_t)j*4096u + koff);
                #pragma unroll
                for (int mf = 0; mf < 3; mf++) {
                    mma16(acc1[mf][2*j],   A[mf][0],A[mf][1],A[mf][2],A[mf][3], b0, b1);
                    mma16(acc1[mf][2*j+1], A[mf][0],A[mf][1],A[mf][2],A[mf][3], b2, b3);
                }
            }
        }
        BARG();   // B2: all warps done reading sA (buffer becomes sH)

        // ---- Epilogue 1: packed f16 bias+relu -> sH, keep own slice in regs ----
        uint32_t hA[3][8], hB[3][8];
        #pragma unroll
        for (int mf=0; mf<3; mf++){
            const uint32_t rb0 = buf_g + (uint32_t)(16*mf + grp) * 512u;
            const uint32_t rb1 = rb0 + 8u * 512u;
            #pragma unroll
            for (int nt=0; nt<8; nt++){
                uint32_t p01 = relu_bias_h2(acc1[mf][nt][0], acc1[mf][nt][1], bh2[nt]);
                uint32_t p23 = relu_bias_h2(acc1[mf][nt][2], acc1[mf][nt][3], bh2[nt]);
                const uint32_t csw = (((uint32_t)(128*wn + nt*16)) ^ (((uint32_t)grp) << 4)) + (uint32_t)(4*tig);
                sts32(rb0 + csw, p01);
                sts32(rb1 + csw, p23);
                hA[mf][nt] = p01; hB[mf][nt] = p23;
            }
        }
        BARG();   // B3: sH ready

        // ---- GEMM2: C2(48x128) = h(48x256) @ W2; own k-slice from registers ----
        float acc2[3][4][4];
        #pragma unroll
        for (int mf=0; mf<3; mf++)
            #pragma unroll
            for (int nt=0; nt<4; nt++)
                #pragma unroll
                for (int i=0;i<4;i++) acc2[mf][nt][i]=0.f;

        #pragma unroll
        for (int s = 0; s < 16; s++) {
            uint32_t A[3][4];
            if ((s >> 2) == wn) {
                const int kkl = s & 3;
                #pragma unroll
                for (int mf = 0; mf < 3; mf++) {
                    A[mf][0] = hA[mf][2*kkl];   A[mf][1] = hB[mf][2*kkl];
                    A[mf][2] = hA[mf][2*kkl+1]; A[mf][3] = hB[mf][2*kkl+1];
                }
            } else {
                const uint32_t ksw = (((uint32_t)(s*32)) + ahi) ^ amask;
                #pragma unroll
                for (int mf = 0; mf < 3; mf++)
                    ldmx4(A[mf][0],A[mf][1],A[mf][2],A[mf][3], a2Base[mf] + ksw);
            }
            const uint32_t koff = (((uint32_t)(s*32)) + bq) ^ bmsk;
            #pragma unroll
            for (int j = 0; j < 2; j++) {
                uint32_t b0,b1,b2,b3;
                ldmx4(b0,b1,b2,b3, b2Ldsm + (uint32_t)j*8192u + koff);
                #pragma unroll
                for (int mf = 0; mf < 3; mf++) {
                    mma16(acc2[mf][2*j],   A[mf][0],A[mf][1],A[mf][2],A[mf][3], b0, b1);
                    mma16(acc2[mf][2*j+1], A[mf][0],A[mf][1],A[mf][2],A[mf][3], b2, b3);
                }
            }
        }

        // ---- Epilogue 2: bias + branch-permuted scatter (per-row p/e, tail-masked) ----
        #pragma unroll
        for (int mf=0; mf<3; mf++){
            const int r0 = 16*mf + grp;
            const int grow0 = rowbase_t + r0;
            const int grow1 = grow0 + 8;
            const int p0r = grow0 >> 13, e0r = grow0 & (NE-1);
            const int p1r = grow1 >> 13, e1r = grow1 & (NE-1);
            const bool v0r = grow0 < NN, v1r = grow1 < NN;
            #pragma unroll
            for (int nt=0; nt<4; nt++){
                const int c0 = nb2 + nt*8 + 2*tig;
                const int br = c0 >> 6, fc = c0 & 63;
                float bz0 = sb2[c0], bz1 = sb2[c0+1];
                if (v0r) {
                    const size_t rowi = (size_t)NN + (size_t)(2*p0r + br) * NE + (size_t)e0r;
                    float2 v0 = { acc2[mf][nt][0] + bz0, acc2[mf][nt][1] + bz1 };
                    *(float2*)(out + rowi * NF + fc) = v0;
                }
                if (v1r) {
                    const size_t rowi = (size_t)NN + (size_t)(2*p1r + br) * NE + (size_t)e1r;
                    float2 v1 = { acc2[mf][nt][2] + bz0, acc2[mf][nt][3] + bz1 };
                    *(float2*)(out + rowi * NF + fc) = v1;
                }
            }
        }
        BARG();   // B4: all warps done reading sH (buffer becomes sA next iter)
    }
    #undef BARG
}

extern "C" void kernel_launch(void* const* d_in, const int* in_sizes, int n_in,
                              void* d_out, int out_size)
{
    const float* x   = (const float*)d_in[0];
    const float* gf  = (const float*)d_in[1];
    const float* W1  = (const float*)d_in[2];
    const float* b1  = (const float*)d_in[3];
    const float* W2  = (const float*)d_in[4];
    const float* b2  = (const float*)d_in[5];
    const int*  pidx = (const int*)d_in[6];
    float* out = (float*)d_out;

    int write_event = (out_size >= (3 * NN * NF + 3 * NN)) ? 1 : 0;

    int dev = 0, nsm = 148;
    cudaGetDevice(&dev);
    cudaDeviceGetAttribute(&nsm, cudaDevAttrMultiProcessorCount, dev);
    if (nsm <= 0 || nsm > 8192) nsm = 148;

    cudaFuncSetAttribute(fused_h16p, cudaFuncAttributeMaxDynamicSharedMemorySize, SMEM_REQ);
    fused_h16p<<<nsm, NTHREADS, SMEM_REQ>>>(x, gf, W1, b1, W2, b2, pidx, out, write_event);
}